// round 4
// baseline (speedup 1.0000x reference)
#include <cuda_runtime.h>
#include <cuda_bf16.h>

// Scratch for intermediate row-dots (no cudaMalloc allowed).
// Problem shapes: B=1024 (<=4096), E=50000 (<=65536).
__device__ float g_hr[4096];      // hr_part[b] + bias
__device__ float g_tail[65536];   // tail_part[e]

// ---------------------------------------------------------------------------
// Warp-per-row dot product: out written to g_hr (with bias added).
// ---------------------------------------------------------------------------
__global__ void hr_dot_kernel(const float* __restrict__ mat,
                              const float* __restrict__ W,
                              const float* __restrict__ bias,
                              int rows, int C) {
    int warp = (blockIdx.x * blockDim.x + threadIdx.x) >> 5;
    int lane = threadIdx.x & 31;
    if (warp >= rows) return;

    const float* row = mat + (size_t)warp * C;
    float acc = 0.0f;
    int C4 = C >> 2;
    if ((C & 3) == 0) {
        const float4* row4 = reinterpret_cast<const float4*>(row);
        const float4* w4   = reinterpret_cast<const float4*>(W);
        for (int k = lane; k < C4; k += 32) {
            float4 a = __ldg(row4 + k);
            float4 b = __ldg(w4 + k);
            acc += a.x * b.x + a.y * b.y + a.z * b.z + a.w * b.w;
        }
    } else {
        for (int k = lane; k < C; k += 32)
            acc += __ldg(row + k) * __ldg(W + k);
    }
#pragma unroll
    for (int off = 16; off; off >>= 1)
        acc += __shfl_xor_sync(0xffffffffu, acc, off);
    if (lane == 0)
        g_hr[warp] = acc + bias[0];
}

// ---------------------------------------------------------------------------
// Warp-per-row dot product: out written to g_tail (no bias).
// ---------------------------------------------------------------------------
__global__ void tail_dot_kernel(const float* __restrict__ mat,
                                const float* __restrict__ W,
                                int rows, int C) {
    int warp = (blockIdx.x * blockDim.x + threadIdx.x) >> 5;
    int lane = threadIdx.x & 31;
    if (warp >= rows) return;

    const float* row = mat + (size_t)warp * C;
    float acc = 0.0f;
    int C4 = C >> 2;
    if ((C & 3) == 0) {
        const float4* row4 = reinterpret_cast<const float4*>(row);
        const float4* w4   = reinterpret_cast<const float4*>(W);
        for (int k = lane; k < C4; k += 32) {
            float4 a = __ldg(row4 + k);
            float4 b = __ldg(w4 + k);
            acc += a.x * b.x + a.y * b.y + a.z * b.z + a.w * b.w;
        }
    } else {
        for (int k = lane; k < C; k += 32)
            acc += __ldg(row + k) * __ldg(W + k);
    }
#pragma unroll
    for (int off = 16; off; off >>= 1)
        acc += __shfl_xor_sync(0xffffffffu, acc, off);
    if (lane == 0)
        g_tail[warp] = acc;
}

// ---------------------------------------------------------------------------
// Broadcast write: out[b*E + e] = g_hr[b] + g_tail[e].
// Vectorized float4 path with streaming stores (output >> L2; tail stays hot).
// gridDim.y = b, gridDim.x covers E/4.
// ---------------------------------------------------------------------------
__global__ void bcast_vec_kernel(float* __restrict__ out, int E4, long long E) {
    int e4 = blockIdx.x * blockDim.x + threadIdx.x;
    if (e4 >= E4) return;
    int b = blockIdx.y;
    float h = g_hr[b];  // uniform per block -> broadcast load
    float4 t = __ldg(reinterpret_cast<const float4*>(g_tail) + e4);
    float4 r = make_float4(t.x + h, t.y + h, t.z + h, t.w + h);
    float4* dst = reinterpret_cast<float4*>(out + (size_t)b * E) + e4;
    __stcs(dst, r);
}

// Scalar fallback for E % 4 != 0.
__global__ void bcast_scalar_kernel(float* __restrict__ out, int E) {
    int e = blockIdx.x * blockDim.x + threadIdx.x;
    if (e >= E) return;
    int b = blockIdx.y;
    out[(size_t)b * E + e] = g_hr[b] + g_tail[e];
}

// Zero any trailing output elements (reference returns (scores, 0)).
__global__ void zero_tail_kernel(float* __restrict__ out, long long start,
                                 long long total) {
    long long i = start + (long long)blockIdx.x * blockDim.x + threadIdx.x;
    if (i < total) out[i] = 0.0f;
}

extern "C" void kernel_launch(void* const* d_in, const int* in_sizes, int n_in,
                              void* d_out, int out_size) {
    const float* hr   = (const float*)d_in[0];  // [B, C]
    const float* tail = (const float*)d_in[1];  // [E, C]
    const float* W    = (const float*)d_in[2];  // [1, 2C]
    const float* bias = (const float*)d_in[3];  // [1]
    float* out = (float*)d_out;

    int C = in_sizes[2] / 2;
    int B = in_sizes[0] / C;
    int E = in_sizes[1] / C;

    // 1) hr_part + bias  (B warps)
    {
        int warps = B;
        int threads = 256;
        int blocks = (warps * 32 + threads - 1) / threads;
        hr_dot_kernel<<<blocks, threads>>>(hr, W, bias, B, C);
    }

    // 2) tail_part  (E warps) — W2 = W + C
    {
        int warps = E;
        int threads = 256;
        int blocks = (warps * 32 + threads - 1) / threads;
        tail_dot_kernel<<<blocks, threads>>>(tail, W + C, E, C);
    }

    // 3) broadcast sum -> out
    if ((E & 3) == 0) {
        int E4 = E >> 2;
        dim3 grid((E4 + 255) / 256, B);
        bcast_vec_kernel<<<grid, 256>>>(out, E4, (long long)E);
    } else {
        dim3 grid((E + 255) / 256, B);
        bcast_scalar_kernel<<<grid, 256>>>(out, E);
    }

    // 4) zero any trailing elements beyond B*E
    long long BE = (long long)B * (long long)E;
    long long total = (long long)out_size;
    if (total > BE) {
        long long extra = total - BE;
        int threads = 256;
        long long blocks = (extra + threads - 1) / threads;
        zero_tail_kernel<<<(unsigned)blocks, threads>>>(out, BE, total);
    }
}

// round 5
// speedup vs baseline: 1.0625x; 1.0625x over previous
#include <cuda_runtime.h>
#include <cuda_bf16.h>

// Scratch for intermediate row-dots (no cudaMalloc allowed).
// Problem shapes: B=1024 (<=4096), E=50000 (<=65536).
__device__ float g_hr[4096];      // hr_part[b] + bias
__device__ float g_tail[65536];   // tail_part[e]

// ---------------------------------------------------------------------------
// Fused warp-per-row dot kernel over B+E rows.
//   row <  B : g_hr[row]    = hr[row,:]   . W1  + bias
//   row >= B : g_tail[row-B]= tail[row-B,:]. W2
// Also zero-fills the trailing [BE, total) region of the output (the
// reference returns (scores, 0), so out_size may exceed B*E slightly).
// ---------------------------------------------------------------------------
__global__ void dots_kernel(const float* __restrict__ hr,
                            const float* __restrict__ tail,
                            const float* __restrict__ W,   // [2C]: W1 | W2
                            const float* __restrict__ bias,
                            int B, int E, int C,
                            float* __restrict__ out,
                            long long zero_start, long long total) {
    int gid  = blockIdx.x * blockDim.x + threadIdx.x;
    int warp = gid >> 5;
    int lane = threadIdx.x & 31;

    // Fold trailing zero-fill into this kernel (tiny: few elements).
    long long zi = zero_start + (long long)gid;
    if (zi < total) out[zi] = 0.0f;

    int rows = B + E;
    if (warp >= rows) return;

    const float* row;
    const float* w;
    if (warp < B) { row = hr   + (size_t)warp * C;       w = W;     }
    else          { row = tail + (size_t)(warp - B) * C; w = W + C; }

    float acc = 0.0f;
    if ((C & 3) == 0) {
        const float4* row4 = reinterpret_cast<const float4*>(row);
        const float4* w4   = reinterpret_cast<const float4*>(w);
        int C4 = C >> 2;
        for (int k = lane; k < C4; k += 32) {
            float4 a = __ldg(row4 + k);
            float4 b = __ldg(w4 + k);
            acc += a.x * b.x + a.y * b.y + a.z * b.z + a.w * b.w;
        }
    } else {
        for (int k = lane; k < C; k += 32)
            acc += __ldg(row + k) * __ldg(w + k);
    }
#pragma unroll
    for (int off = 16; off; off >>= 1)
        acc += __shfl_xor_sync(0xffffffffu, acc, off);

    if (lane == 0) {
        if (warp < B) g_hr[warp] = acc + bias[0];
        else          g_tail[warp - B] = acc;
    }
}

// ---------------------------------------------------------------------------
// Broadcast write: out[b*E + e] = g_hr[b] + g_tail[e].
// float4 streaming stores; g_tail (200 KB) stays L2-hot across all b-rows,
// the 205 MB output streams past L2 via .cs.
// gridDim.y = b, gridDim.x covers E/4.
// ---------------------------------------------------------------------------
__global__ void bcast_vec_kernel(float* __restrict__ out, int E4, long long E) {
    int e4 = blockIdx.x * blockDim.x + threadIdx.x;
    if (e4 >= E4) return;
    int b = blockIdx.y;
    float h = g_hr[b];  // uniform per block -> broadcast load
    float4 t = __ldg(reinterpret_cast<const float4*>(g_tail) + e4);
    float4 r = make_float4(t.x + h, t.y + h, t.z + h, t.w + h);
    float4* dst = reinterpret_cast<float4*>(out + (size_t)b * E) + e4;
    __stcs(dst, r);
}

// Scalar fallback for E % 4 != 0.
__global__ void bcast_scalar_kernel(float* __restrict__ out, int E) {
    int e = blockIdx.x * blockDim.x + threadIdx.x;
    if (e >= E) return;
    int b = blockIdx.y;
    out[(size_t)b * E + e] = g_hr[b] + g_tail[e];
}

extern "C" void kernel_launch(void* const* d_in, const int* in_sizes, int n_in,
                              void* d_out, int out_size) {
    const float* hr   = (const float*)d_in[0];  // [B, C]
    const float* tail = (const float*)d_in[1];  // [E, C]
    const float* W    = (const float*)d_in[2];  // [1, 2C]
    const float* bias = (const float*)d_in[3];  // [1]
    float* out = (float*)d_out;

    int C = in_sizes[2] / 2;
    int B = in_sizes[0] / C;
    int E = in_sizes[1] / C;

    long long BE    = (long long)B * (long long)E;
    long long total = (long long)out_size;

    // 1) fused hr+tail dots (+ trailing zero-fill)
    {
        int rows = B + E;
        int threads = 256;
        long long lanes = (long long)rows * 32;
        // ensure enough threads to also cover the zero-fill span
        long long extra = (total > BE) ? (total - BE) : 0;
        if (extra > lanes) lanes = extra;
        int blocks = (int)((lanes + threads - 1) / threads);
        dots_kernel<<<blocks, threads>>>(hr, tail, W, bias, B, E, C,
                                         out, BE, total);
    }

    // 2) broadcast sum -> out
    if ((E & 3) == 0) {
        int E4 = E >> 2;
        dim3 grid((E4 + 255) / 256, B);
        bcast_vec_kernel<<<grid, 256>>>(out, E4, (long long)E);
    } else {
        dim3 grid((E + 255) / 256, B);
        bcast_scalar_kernel<<<grid, 256>>>(out, E);
    }
}

// round 6
// speedup vs baseline: 1.1932x; 1.1230x over previous
#include <cuda_runtime.h>
#include <cuda_bf16.h>

// Scratch for intermediate row-dots (no cudaMalloc allowed).
// Problem shapes: B=1024 (<=4096), E=50000 (<=65536).
__device__ float g_hr[4096];      // hr_part[b] + bias
__device__ float g_tail[65536];   // tail_part[e]

// ---------------------------------------------------------------------------
// Fused warp-per-row dot kernel over B+E rows.
//   row <  B : g_hr[row]     = hr[row,:]    . W1 + bias
//   row >= B : g_tail[row-B] = tail[row-B,:]. W2
// Also zero-fills the trailing [BE, total) region of the output.
// ---------------------------------------------------------------------------
__global__ void dots_kernel(const float* __restrict__ hr,
                            const float* __restrict__ tail,
                            const float* __restrict__ W,   // [2C]: W1 | W2
                            const float* __restrict__ bias,
                            int B, int E, int C,
                            float* __restrict__ out,
                            long long zero_start, long long total) {
    int gid  = blockIdx.x * blockDim.x + threadIdx.x;
    int warp = gid >> 5;
    int lane = threadIdx.x & 31;

    // Fold trailing zero-fill into this kernel (tiny: few elements).
    long long zi = zero_start + (long long)gid;
    if (zi < total) out[zi] = 0.0f;

    int rows = B + E;
    if (warp >= rows) return;

    const float* row;
    const float* w;
    if (warp < B) { row = hr   + (size_t)warp * C;       w = W;     }
    else          { row = tail + (size_t)(warp - B) * C; w = W + C; }

    float acc = 0.0f;
    if ((C & 3) == 0) {
        const float4* row4 = reinterpret_cast<const float4*>(row);
        const float4* w4   = reinterpret_cast<const float4*>(w);
        int C4 = C >> 2;
        for (int k = lane; k < C4; k += 32) {
            float4 a = __ldg(row4 + k);
            float4 b = __ldg(w4 + k);
            acc += a.x * b.x + a.y * b.y + a.z * b.z + a.w * b.w;
        }
    } else {
        for (int k = lane; k < C; k += 32)
            acc += __ldg(row + k) * __ldg(w + k);
    }
#pragma unroll
    for (int off = 16; off; off >>= 1)
        acc += __shfl_xor_sync(0xffffffffu, acc, off);

    if (lane == 0) {
        if (warp < B) g_hr[warp] = acc + bias[0];
        else          g_tail[warp - B] = acc;
    }
}

// ---------------------------------------------------------------------------
// Broadcast write, b-tiled: each thread loads tail4[e4] ONCE and stores it
// (plus per-row h) to BTILE consecutive b-rows. Cuts L2 read traffic by
// BTILE x and gives each thread BTILE independent streaming stores.
//   gridDim.y = B / BTILE (ceil), gridDim.x covers E/4.
// ---------------------------------------------------------------------------
#define BTILE 8

__global__ void bcast_vec_kernel(float* __restrict__ out, int E4, long long E,
                                 int B) {
    __shared__ float sh[BTILE];
    int b0 = blockIdx.y * BTILE;
    if (threadIdx.x < BTILE) {
        int b = b0 + threadIdx.x;
        sh[threadIdx.x] = (b < B) ? g_hr[b] : 0.0f;
    }
    __syncthreads();

    int e4 = blockIdx.x * blockDim.x + threadIdx.x;
    if (e4 >= E4) return;

    float4 t = __ldg(reinterpret_cast<const float4*>(g_tail) + e4);

    float4* base = reinterpret_cast<float4*>(out + (size_t)b0 * E) + e4;
    long long rowstride4 = E >> 2;  // float4 elements per row

    int nb = B - b0;
    if (nb >= BTILE) {
#pragma unroll
        for (int i = 0; i < BTILE; i++) {
            float h = sh[i];
            float4 r = make_float4(t.x + h, t.y + h, t.z + h, t.w + h);
            __stcs(base + (long long)i * rowstride4, r);
        }
    } else {
        for (int i = 0; i < nb; i++) {
            float h = sh[i];
            float4 r = make_float4(t.x + h, t.y + h, t.z + h, t.w + h);
            __stcs(base + (long long)i * rowstride4, r);
        }
    }
}

// Scalar fallback for E % 4 != 0.
__global__ void bcast_scalar_kernel(float* __restrict__ out, int E) {
    int e = blockIdx.x * blockDim.x + threadIdx.x;
    if (e >= E) return;
    int b = blockIdx.y;
    out[(size_t)b * E + e] = g_hr[b] + g_tail[e];
}

extern "C" void kernel_launch(void* const* d_in, const int* in_sizes, int n_in,
                              void* d_out, int out_size) {
    const float* hr   = (const float*)d_in[0];  // [B, C]
    const float* tail = (const float*)d_in[1];  // [E, C]
    const float* W    = (const float*)d_in[2];  // [1, 2C]
    const float* bias = (const float*)d_in[3];  // [1]
    float* out = (float*)d_out;

    int C = in_sizes[2] / 2;
    int B = in_sizes[0] / C;
    int E = in_sizes[1] / C;

    long long BE    = (long long)B * (long long)E;
    long long total = (long long)out_size;

    // 1) fused hr+tail dots (+ trailing zero-fill)
    {
        int rows = B + E;
        int threads = 256;
        long long lanes = (long long)rows * 32;
        long long extra = (total > BE) ? (total - BE) : 0;
        if (extra > lanes) lanes = extra;
        int blocks = (int)((lanes + threads - 1) / threads);
        dots_kernel<<<blocks, threads>>>(hr, tail, W, bias, B, E, C,
                                         out, BE, total);
    }

    // 2) broadcast sum -> out
    if ((E & 3) == 0) {
        int E4 = E >> 2;
        dim3 grid((E4 + 255) / 256, (B + BTILE - 1) / BTILE);
        bcast_vec_kernel<<<grid, 256>>>(out, E4, (long long)E, B);
    } else {
        dim3 grid((E + 255) / 256, B);
        bcast_scalar_kernel<<<grid, 256>>>(out, E);
    }
}